// round 2
// baseline (speedup 1.0000x reference)
#include <cuda_runtime.h>
#include <math.h>

// Problem dims (fixed per reference)
constexpr int S = 512;
constexpr int B = 256;
constexpr int I = 512;
constexpr int H = 512;
constexpr int M1 = S * B;        // 131072 rows for phase-1 GEMM
constexpr int BH = B * H;        // 131072 elements per timestep

// ---------------------------------------------------------------------------
// Phase 1: xV = x @ Vw^T + Vb
//   A: (M1, I) row-major, W: (H, I) row-major, C: (M1, H) row-major
//   BM=BN=128, BK=16, 256 threads, 8x8 register micro-tile per thread.
// ---------------------------------------------------------------------------
__global__ void __launch_bounds__(256) phase1_gemm(
    const float* __restrict__ A,
    const float* __restrict__ W,
    const float* __restrict__ bias,
    float* __restrict__ C)
{
    constexpr int BM = 128, BN = 128, BK = 16;
    constexpr int K = I;
    constexpr int PAD = 4;                       // keep 16B alignment of rows
    __shared__ float As[BK][BM + PAD];
    __shared__ float Bs[BK][BN + PAD];

    const int tid = threadIdx.x;
    const int bn = blockIdx.x;                   // H/128 = 4
    const int bm = blockIdx.y;                   // M1/128 = 1024

    const float* Ap = A + (size_t)bm * BM * K;
    const float* Wp = W + (size_t)bn * BN * K;

    const int ty = tid / 16;                     // 0..15 -> 8 rows each
    const int tx = tid % 16;                     // 0..15 -> 8 cols each

    float acc[8][8];
    #pragma unroll
    for (int i = 0; i < 8; i++)
        #pragma unroll
        for (int j = 0; j < 8; j++) acc[i][j] = 0.0f;

    for (int k0 = 0; k0 < K; k0 += BK) {
        // Load 128x16 tiles of A and W (512 float4 each; 2 per thread)
        #pragma unroll
        for (int l = 0; l < 2; l++) {
            int f   = tid + l * 256;             // 0..511
            int row = f >> 2;                    // 0..127
            int c4  = (f & 3) * 4;               // 0,4,8,12
            float4 av = *reinterpret_cast<const float4*>(Ap + (size_t)row * K + k0 + c4);
            As[c4 + 0][row] = av.x;
            As[c4 + 1][row] = av.y;
            As[c4 + 2][row] = av.z;
            As[c4 + 3][row] = av.w;
            float4 bv = *reinterpret_cast<const float4*>(Wp + (size_t)row * K + k0 + c4);
            Bs[c4 + 0][row] = bv.x;
            Bs[c4 + 1][row] = bv.y;
            Bs[c4 + 2][row] = bv.z;
            Bs[c4 + 3][row] = bv.w;
        }
        __syncthreads();

        #pragma unroll
        for (int k = 0; k < BK; k++) {
            float ar[8], br[8];
            *reinterpret_cast<float4*>(ar)     = *reinterpret_cast<const float4*>(&As[k][ty * 8]);
            *reinterpret_cast<float4*>(ar + 4) = *reinterpret_cast<const float4*>(&As[k][ty * 8 + 4]);
            *reinterpret_cast<float4*>(br)     = *reinterpret_cast<const float4*>(&Bs[k][tx * 8]);
            *reinterpret_cast<float4*>(br + 4) = *reinterpret_cast<const float4*>(&Bs[k][tx * 8 + 4]);
            #pragma unroll
            for (int i = 0; i < 8; i++)
                #pragma unroll
                for (int j = 0; j < 8; j++)
                    acc[i][j] = fmaf(ar[i], br[j], acc[i][j]);
        }
        __syncthreads();
    }

    // Epilogue: add bias, store
    const int rowb = bm * BM + ty * 8;
    const int colb = bn * BN + tx * 8;
    float bvals[8];
    #pragma unroll
    for (int j = 0; j < 8; j++) bvals[j] = bias[colb + j];

    #pragma unroll
    for (int i = 0; i < 8; i++) {
        float* cp = C + (size_t)(rowb + i) * H + colb;
        float4 v0, v1;
        v0.x = acc[i][0] + bvals[0];
        v0.y = acc[i][1] + bvals[1];
        v0.z = acc[i][2] + bvals[2];
        v0.w = acc[i][3] + bvals[3];
        v1.x = acc[i][4] + bvals[4];
        v1.y = acc[i][5] + bvals[5];
        v1.z = acc[i][6] + bvals[6];
        v1.w = acc[i][7] + bvals[7];
        *reinterpret_cast<float4*>(cp)     = v0;
        *reinterpret_cast<float4*>(cp + 4) = v1;
    }
}

// ---------------------------------------------------------------------------
// Step t=0: h_0 = tanh(xV_0 + Wb)   (h_{-1} = 0, so no GEMM)
// ---------------------------------------------------------------------------
__global__ void __launch_bounds__(256) bias_tanh_kernel(
    float* __restrict__ C, const float* __restrict__ bias)
{
    int i = blockIdx.x * blockDim.x + threadIdx.x;   // BH threads total
    C[i] = tanhf(C[i] + bias[i & (H - 1)]);
}

// ---------------------------------------------------------------------------
// Step t>0: Cio = tanh(Hprev @ W^T + Cio + Wb)
//   Hprev: (B, H), W: (H, H), Cio: (B, H) holds xV_t on input, h_t on output.
//   BM=BN=32, BK=32, 128 threads, 2x4 micro-tile; grid = (H/32, B/32) = (16,8)
//   = 128 CTAs so most SMs get work despite the tiny per-step problem.
// ---------------------------------------------------------------------------
__global__ void __launch_bounds__(128) step_kernel(
    const float* __restrict__ Hprev,
    const float* __restrict__ W,
    const float* __restrict__ bias,
    float* __restrict__ Cio)
{
    constexpr int BM = 32, BN = 32, BK = 32;
    constexpr int K = H;
    constexpr int PAD = 4;
    __shared__ float As[BK][BM + PAD];
    __shared__ float Bs[BK][BN + PAD];

    const int tid = threadIdx.x;
    const int bn = blockIdx.x;       // column tile (H/32 = 16)
    const int bm = blockIdx.y;       // row tile    (B/32 = 8)

    const float* Ap = Hprev + (size_t)bm * BM * K;
    const float* Wp = W     + (size_t)bn * BN * K;

    const int ty = tid / 8;          // 0..15 -> 2 rows each
    const int tx = tid % 8;          // 0..7  -> 4 cols each

    float acc[2][4];
    #pragma unroll
    for (int i = 0; i < 2; i++)
        #pragma unroll
        for (int j = 0; j < 4; j++) acc[i][j] = 0.0f;

    for (int k0 = 0; k0 < K; k0 += BK) {
        // 32x32 tiles = 256 float4; 2 per thread
        #pragma unroll
        for (int l = 0; l < 2; l++) {
            int f   = tid + l * 128;     // 0..255
            int row = f >> 3;            // 0..31
            int c4  = (f & 7) * 4;       // 0..28
            float4 av = *reinterpret_cast<const float4*>(Ap + (size_t)row * K + k0 + c4);
            As[c4 + 0][row] = av.x;
            As[c4 + 1][row] = av.y;
            As[c4 + 2][row] = av.z;
            As[c4 + 3][row] = av.w;
            float4 bv = *reinterpret_cast<const float4*>(Wp + (size_t)row * K + k0 + c4);
            Bs[c4 + 0][row] = bv.x;
            Bs[c4 + 1][row] = bv.y;
            Bs[c4 + 2][row] = bv.z;
            Bs[c4 + 3][row] = bv.w;
        }
        __syncthreads();

        #pragma unroll
        for (int k = 0; k < BK; k++) {
            float a0 = As[k][ty * 2 + 0];
            float a1 = As[k][ty * 2 + 1];
            float br[4];
            *reinterpret_cast<float4*>(br) = *reinterpret_cast<const float4*>(&Bs[k][tx * 4]);
            #pragma unroll
            for (int j = 0; j < 4; j++) {
                acc[0][j] = fmaf(a0, br[j], acc[0][j]);
                acc[1][j] = fmaf(a1, br[j], acc[1][j]);
            }
        }
        __syncthreads();
    }

    // Epilogue: add xV_t (resident in Cio) + bias, tanh, store in place.
    const int rowb = bm * BM + ty * 2;
    const int colb = bn * BN + tx * 4;
    float4 bv = *reinterpret_cast<const float4*>(bias + colb);

    #pragma unroll
    for (int i = 0; i < 2; i++) {
        float* cp = Cio + (size_t)(rowb + i) * H + colb;
        float4 c = *reinterpret_cast<const float4*>(cp);
        float4 v;
        v.x = tanhf(acc[i][0] + c.x + bv.x);
        v.y = tanhf(acc[i][1] + c.y + bv.y);
        v.z = tanhf(acc[i][2] + c.z + bv.z);
        v.w = tanhf(acc[i][3] + c.w + bv.w);
        *reinterpret_cast<float4*>(cp) = v;
    }
}

// ---------------------------------------------------------------------------
// Copy h_{S-1} to the h_last slot at the tail of the output buffer.
// ---------------------------------------------------------------------------
__global__ void __launch_bounds__(256) copy_last_kernel(float* __restrict__ out)
{
    int i = blockIdx.x * blockDim.x + threadIdx.x;   // BH threads
    out[(size_t)S * BH + i] = out[(size_t)(S - 1) * BH + i];
}

// ---------------------------------------------------------------------------
// kernel_launch
// Inputs (metadata order): x (S,B,I), Vw (H,I), Vb (H), Ww (H,H), Wb (H)
// Output: h_seq (S,B,H) followed by h_last (B,H), fp32.
// ---------------------------------------------------------------------------
extern "C" void kernel_launch(void* const* d_in, const int* in_sizes, int n_in,
                              void* d_out, int out_size)
{
    const float* x  = (const float*)d_in[0];
    const float* Vw = (const float*)d_in[1];
    const float* Vb = (const float*)d_in[2];
    const float* Ww = (const float*)d_in[3];
    const float* Wb = (const float*)d_in[4];
    float* out = (float*)d_out;

    // Phase 1: xV for all timesteps, written directly into the h_seq region.
    dim3 g1(H / 128, M1 / 128);      // (4, 1024)
    phase1_gemm<<<g1, 256>>>(x, Vw, Vb, out);

    // Step 0: h_0 = tanh(xV_0 + Wb)
    bias_tanh_kernel<<<BH / 256, 256>>>(out, Wb);

    // Steps 1..S-1 (sequential recurrence, in-place over the h_seq region)
    dim3 gs(H / 32, B / 32);         // (16, 8) = 128 CTAs
    for (int t = 1; t < S; ++t) {
        step_kernel<<<gs, 128>>>(out + (size_t)(t - 1) * BH, Ww, Wb,
                                 out + (size_t)t * BH);
    }

    // h_last = h_{S-1}
    copy_last_kernel<<<BH / 256, 256>>>(out);
}

// round 3
// speedup vs baseline: 1.6448x; 1.6448x over previous
#include <cuda_runtime.h>
#include <math.h>

// Problem dims (fixed per reference)
constexpr int S = 512;
constexpr int B = 256;
constexpr int I = 512;
constexpr int H = 512;
constexpr int M1 = S * B;        // 131072 rows for phase-1 GEMM
constexpr int BH = B * H;        // 131072 elements per timestep

// ---------------------------------------------------------------------------
// Packed fp32x2 helpers (Blackwell FFMA2 path — bit-exact IEEE fma per lane)
// ---------------------------------------------------------------------------
__device__ __forceinline__ void ffma2(unsigned long long& d,
                                      unsigned long long a,
                                      unsigned long long b) {
    asm("fma.rn.f32x2 %0, %1, %2, %0;" : "+l"(d) : "l"(a), "l"(b));
}
__device__ __forceinline__ unsigned long long splat2(float x) {
    unsigned long long r;
    asm("mov.b64 %0, {%1, %1};" : "=l"(r) : "f"(x));
    return r;
}
__device__ __forceinline__ void unpack2(unsigned long long v, float& lo, float& hi) {
    asm("mov.b64 {%0, %1}, %2;" : "=f"(lo), "=f"(hi) : "l"(v));
}

// ---------------------------------------------------------------------------
// Grid-wide barrier state. Counter is monotonically increasing within one
// kernel run; a prologue reset kernel zeroes it each graph replay, so the
// persistent kernel is deterministic across replays.
// ---------------------------------------------------------------------------
__device__ unsigned int g_ctr;

__global__ void reset_ctr() { g_ctr = 0u; }

// ---------------------------------------------------------------------------
// Phase 1: xV = x @ Vw^T + Vb  (unchanged from round 1; ~0.5ms, not the
// bottleneck this round)
// ---------------------------------------------------------------------------
__global__ void __launch_bounds__(256) phase1_gemm(
    const float* __restrict__ A,
    const float* __restrict__ W,
    const float* __restrict__ bias,
    float* __restrict__ C)
{
    constexpr int BM = 128, BN = 128, BK = 16;
    constexpr int K = I;
    constexpr int PAD = 4;
    __shared__ float As[BK][BM + PAD];
    __shared__ float Bs[BK][BN + PAD];

    const int tid = threadIdx.x;
    const int bn = blockIdx.x;
    const int bm = blockIdx.y;

    const float* Ap = A + (size_t)bm * BM * K;
    const float* Wp = W + (size_t)bn * BN * K;

    const int ty = tid / 16;
    const int tx = tid % 16;

    float acc[8][8];
    #pragma unroll
    for (int i = 0; i < 8; i++)
        #pragma unroll
        for (int j = 0; j < 8; j++) acc[i][j] = 0.0f;

    for (int k0 = 0; k0 < K; k0 += BK) {
        #pragma unroll
        for (int l = 0; l < 2; l++) {
            int f   = tid + l * 256;
            int row = f >> 2;
            int c4  = (f & 3) * 4;
            float4 av = *reinterpret_cast<const float4*>(Ap + (size_t)row * K + k0 + c4);
            As[c4 + 0][row] = av.x;
            As[c4 + 1][row] = av.y;
            As[c4 + 2][row] = av.z;
            As[c4 + 3][row] = av.w;
            float4 bv = *reinterpret_cast<const float4*>(Wp + (size_t)row * K + k0 + c4);
            Bs[c4 + 0][row] = bv.x;
            Bs[c4 + 1][row] = bv.y;
            Bs[c4 + 2][row] = bv.z;
            Bs[c4 + 3][row] = bv.w;
        }
        __syncthreads();

        #pragma unroll
        for (int k = 0; k < BK; k++) {
            float ar[8], br[8];
            *reinterpret_cast<float4*>(ar)     = *reinterpret_cast<const float4*>(&As[k][ty * 8]);
            *reinterpret_cast<float4*>(ar + 4) = *reinterpret_cast<const float4*>(&As[k][ty * 8 + 4]);
            *reinterpret_cast<float4*>(br)     = *reinterpret_cast<const float4*>(&Bs[k][tx * 8]);
            *reinterpret_cast<float4*>(br + 4) = *reinterpret_cast<const float4*>(&Bs[k][tx * 8 + 4]);
            #pragma unroll
            for (int i = 0; i < 8; i++)
                #pragma unroll
                for (int j = 0; j < 8; j++)
                    acc[i][j] = fmaf(ar[i], br[j], acc[i][j]);
        }
        __syncthreads();
    }

    const int rowb = bm * BM + ty * 8;
    const int colb = bn * BN + tx * 8;
    float bvals[8];
    #pragma unroll
    for (int j = 0; j < 8; j++) bvals[j] = bias[colb + j];

    #pragma unroll
    for (int i = 0; i < 8; i++) {
        float* cp = C + (size_t)(rowb + i) * H + colb;
        float4 v0, v1;
        v0.x = acc[i][0] + bvals[0];
        v0.y = acc[i][1] + bvals[1];
        v0.z = acc[i][2] + bvals[2];
        v0.w = acc[i][3] + bvals[3];
        v1.x = acc[i][4] + bvals[4];
        v1.y = acc[i][5] + bvals[5];
        v1.z = acc[i][6] + bvals[6];
        v1.w = acc[i][7] + bvals[7];
        *reinterpret_cast<float4*>(cp)     = v0;
        *reinterpret_cast<float4*>(cp + 4) = v1;
    }
}

// ---------------------------------------------------------------------------
// Persistent recurrence kernel: 128 CTAs x 128 threads, one CTA per (32x32)
// output tile of (B=256, H=512). W^T panel lives in smem for the whole run.
// All 512 timesteps in one launch; grid barrier between steps.
//
// Dynamic smem layout:
//   [0,      65536)  float  Bs[512][32]        : Bs[k*32+n] = Ww[bn*32+n][k]
//   [65536, 82432)   u64   As2[2][32][33]      : double-buffered, pre-splatted
// ---------------------------------------------------------------------------
constexpr int SMEM_BS_FLOATS = 512 * 32;                 // 16384 floats = 64KB
constexpr int SMEM_BYTES = SMEM_BS_FLOATS * 4 + 2 * 32 * 33 * 8;  // 82432

__global__ void __launch_bounds__(128, 1) rnn_steps(
    const float* __restrict__ Ww,
    const float* __restrict__ Wb,
    float* __restrict__ io)          // output buffer: S slots of (B,H) + h_last
{
    extern __shared__ char smem_raw[];
    float* Bs = reinterpret_cast<float*>(smem_raw);
    unsigned long long* As2 =
        reinterpret_cast<unsigned long long*>(smem_raw + SMEM_BS_FLOATS * 4);

    const int tid  = threadIdx.x;
    const int bx   = blockIdx.x;
    const int bm   = bx >> 4;              // 0..7   : B tile
    const int bn   = bx & 15;              // 0..15  : H tile
    const int ty   = tid >> 3;             // 0..15
    const int tx   = tid & 7;              // 0..7
    const int r0   = bm * 32 + ty * 2;     // global output row (and +1)
    const int colb = bn * 32 + tx * 4;     // global output col (4 wide)

    // Chunk-load lane mapping (32 rows x 32 k per chunk, 2 float4 per thread)
    const int lrow0 = tid >> 3;            // 0..15  (second load: +16)
    const int lc0   = (tid & 7) * 4;       // 0,4,...,28

    // ---- Load W^T panel into smem once (Bs[k][n] = Ww[bn*32+n][k]) ----
    for (int i = tid * 4; i < 32 * 512; i += 128 * 4) {
        int nl = i >> 9;                   // 0..31
        int k4 = i & 511;
        float4 v = *reinterpret_cast<const float4*>(Ww + (size_t)(bn * 32 + nl) * 512 + k4);
        Bs[(k4 + 0) * 32 + nl] = v.x;
        Bs[(k4 + 1) * 32 + nl] = v.y;
        Bs[(k4 + 2) * 32 + nl] = v.z;
        Bs[(k4 + 3) * 32 + nl] = v.w;
    }
    const float4 wb4 = *reinterpret_cast<const float4*>(Wb + colb);
    __syncthreads();

    // ---- t = 0 : h_0 = tanh(xV_0 + Wb) ----
    {
        float* ct = io;                    // slot 0
        float4 xv0 = __ldcg(reinterpret_cast<const float4*>(ct + (size_t)r0 * H + colb));
        float4 xv1 = __ldcg(reinterpret_cast<const float4*>(ct + (size_t)(r0 + 1) * H + colb));
        float4 h0, h1;
        h0.x = tanhf(xv0.x + wb4.x); h0.y = tanhf(xv0.y + wb4.y);
        h0.z = tanhf(xv0.z + wb4.z); h0.w = tanhf(xv0.w + wb4.w);
        h1.x = tanhf(xv1.x + wb4.x); h1.y = tanhf(xv1.y + wb4.y);
        h1.z = tanhf(xv1.z + wb4.z); h1.w = tanhf(xv1.w + wb4.w);
        *reinterpret_cast<float4*>(ct + (size_t)r0 * H + colb)       = h0;
        *reinterpret_cast<float4*>(ct + (size_t)(r0 + 1) * H + colb) = h1;
    }

    // ---- steps t = 1 .. S-1 ----
    for (int t = 1; t < S; ++t) {
        // grid barrier: h_{t-1} fully written before anyone reads it
        __syncthreads();
        if (tid == 0) {
            __threadfence();
            atomicAdd(&g_ctr, 1u);
            const unsigned target = (unsigned)t * 128u;
            while (*((volatile unsigned int*)&g_ctr) < target) { }
            __threadfence();
        }
        __syncthreads();

        const float* hp = io + (size_t)(t - 1) * BH;   // A panel (prev h)
        float*       ct = io + (size_t)t * BH;         // xV_t in, h_t out

        // prefetch this thread's xV tile early (DRAM-latency hidden by GEMM)
        float4 xv0 = __ldcg(reinterpret_cast<const float4*>(ct + (size_t)r0 * H + colb));
        float4 xv1 = __ldcg(reinterpret_cast<const float4*>(ct + (size_t)(r0 + 1) * H + colb));

        unsigned long long acc00 = 0ull, acc01 = 0ull, acc10 = 0ull, acc11 = 0ull;

        const float* apan = hp + (size_t)(bm * 32) * 512;

        // preload chunk 0
        float4 p0 = __ldcg(reinterpret_cast<const float4*>(apan + (size_t)lrow0 * 512 + lc0));
        float4 p1 = __ldcg(reinterpret_cast<const float4*>(apan + (size_t)(lrow0 + 16) * 512 + lc0));
        {
            unsigned long long* dst = As2;   // buf 0
            dst[(lc0 + 0) * 33 + lrow0] = splat2(p0.x);
            dst[(lc0 + 1) * 33 + lrow0] = splat2(p0.y);
            dst[(lc0 + 2) * 33 + lrow0] = splat2(p0.z);
            dst[(lc0 + 3) * 33 + lrow0] = splat2(p0.w);
            dst[(lc0 + 0) * 33 + lrow0 + 16] = splat2(p1.x);
            dst[(lc0 + 1) * 33 + lrow0 + 16] = splat2(p1.y);
            dst[(lc0 + 2) * 33 + lrow0 + 16] = splat2(p1.z);
            dst[(lc0 + 3) * 33 + lrow0 + 16] = splat2(p1.w);
        }
        __syncthreads();

        #pragma unroll 1
        for (int c = 0; c < 16; ++c) {
            const int buf = c & 1;
            if (c < 15) {
                const int k0n = (c + 1) * 32;
                p0 = __ldcg(reinterpret_cast<const float4*>(apan + (size_t)lrow0 * 512 + k0n + lc0));
                p1 = __ldcg(reinterpret_cast<const float4*>(apan + (size_t)(lrow0 + 16) * 512 + k0n + lc0));
            }

            const unsigned long long* ab = As2 + buf * (32 * 33);
            const float* bb = Bs + (c * 32) * 32;
            #pragma unroll
            for (int kk = 0; kk < 32; ++kk) {
                unsigned long long a0 = ab[kk * 33 + ty * 2];
                unsigned long long a1 = ab[kk * 33 + ty * 2 + 1];
                ulonglong2 b = *reinterpret_cast<const ulonglong2*>(bb + kk * 32 + tx * 4);
                ffma2(acc00, a0, b.x);
                ffma2(acc01, a0, b.y);
                ffma2(acc10, a1, b.x);
                ffma2(acc11, a1, b.y);
            }

            if (c < 15) {
                __syncthreads();           // everyone done reading buf^1
                unsigned long long* dst = As2 + (buf ^ 1) * (32 * 33);
                dst[(lc0 + 0) * 33 + lrow0] = splat2(p0.x);
                dst[(lc0 + 1) * 33 + lrow0] = splat2(p0.y);
                dst[(lc0 + 2) * 33 + lrow0] = splat2(p0.z);
                dst[(lc0 + 3) * 33 + lrow0] = splat2(p0.w);
                dst[(lc0 + 0) * 33 + lrow0 + 16] = splat2(p1.x);
                dst[(lc0 + 1) * 33 + lrow0 + 16] = splat2(p1.y);
                dst[(lc0 + 2) * 33 + lrow0 + 16] = splat2(p1.z);
                dst[(lc0 + 3) * 33 + lrow0 + 16] = splat2(p1.w);
                __syncthreads();           // buf^1 filled before next compute
            }
        }

        // epilogue: h_t = tanh(acc + xV_t + Wb)
        float a00l, a00h, a01l, a01h, a10l, a10h, a11l, a11h;
        unpack2(acc00, a00l, a00h);
        unpack2(acc01, a01l, a01h);
        unpack2(acc10, a10l, a10h);
        unpack2(acc11, a11l, a11h);

        float4 h0, h1;
        h0.x = tanhf(a00l + xv0.x + wb4.x);
        h0.y = tanhf(a00h + xv0.y + wb4.y);
        h0.z = tanhf(a01l + xv0.z + wb4.z);
        h0.w = tanhf(a01h + xv0.w + wb4.w);
        h1.x = tanhf(a10l + xv1.x + wb4.x);
        h1.y = tanhf(a10h + xv1.y + wb4.y);
        h1.z = tanhf(a11l + xv1.z + wb4.z);
        h1.w = tanhf(a11h + xv1.w + wb4.w);

        *reinterpret_cast<float4*>(ct + (size_t)r0 * H + colb)       = h0;
        *reinterpret_cast<float4*>(ct + (size_t)(r0 + 1) * H + colb) = h1;

        if (t == S - 1) {
            float* lastp = io + (size_t)S * BH;
            *reinterpret_cast<float4*>(lastp + (size_t)r0 * H + colb)       = h0;
            *reinterpret_cast<float4*>(lastp + (size_t)(r0 + 1) * H + colb) = h1;
        }
    }
}

// ---------------------------------------------------------------------------
// kernel_launch
// Inputs: x (S,B,I), Vw (H,I), Vb (H), Ww (H,H), Wb (H)
// Output: h_seq (S,B,H) followed by h_last (B,H), fp32.
// ---------------------------------------------------------------------------
extern "C" void kernel_launch(void* const* d_in, const int* in_sizes, int n_in,
                              void* d_out, int out_size)
{
    const float* x  = (const float*)d_in[0];
    const float* Vw = (const float*)d_in[1];
    const float* Vb = (const float*)d_in[2];
    const float* Ww = (const float*)d_in[3];
    const float* Wb = (const float*)d_in[4];
    float* out = (float*)d_out;

    static bool attr_done = false;
    if (!attr_done) {
        cudaFuncSetAttribute(rnn_steps,
                             cudaFuncAttributeMaxDynamicSharedMemorySize,
                             SMEM_BYTES);
        attr_done = true;
    }

    // Barrier counter reset (stream-ordered; keeps graph replays deterministic)
    reset_ctr<<<1, 1>>>();

    // Phase 1: xV for all timesteps, written into the h_seq region.
    dim3 g1(H / 128, M1 / 128);
    phase1_gemm<<<g1, 256>>>(x, Vw, Vb, out);

    // Phase 2: all 512 recurrence steps in one persistent kernel.
    rnn_steps<<<128, 128, SMEM_BYTES>>>(Ww, Wb, out);
}

// round 5
// speedup vs baseline: 2.7435x; 1.6679x over previous
#include <cuda_runtime.h>
#include <cuda_bf16.h>
#include <math.h>
#include <stdint.h>

// Problem dims (fixed per reference)
constexpr int S = 512;
constexpr int B = 256;
constexpr int I = 512;
constexpr int H = 512;
constexpr int M1 = S * B;
constexpr int BH = B * H;

// ===========================================================================
// Static device scratch (allocation-free)
// ===========================================================================
__device__ uint32_t g_hl[2][BH];        // packed {bf16 hi<<16 | bf16 lo} h planes
__device__ uint32_t g_whl[H * H];       // packed {hi|lo} of Ww
__device__ unsigned int g_bar[8];       // per-bm-group barrier counters

__device__ __forceinline__ uint32_t pack_hl(float x) {
    __nv_bfloat16 h = __float2bfloat16(x);
    float r = x - __bfloat162float(h);
    __nv_bfloat16 l = __float2bfloat16(r);
    return (((uint32_t)__bfloat16_as_ushort(h)) << 16) |
           (uint32_t)__bfloat16_as_ushort(l);
}

__global__ void reset_ctr() {
    if (threadIdx.x < 8) g_bar[threadIdx.x] = 0u;
}

__global__ void __launch_bounds__(256) convert_W(const float* __restrict__ Ww) {
    int i = blockIdx.x * blockDim.x + threadIdx.x;
    if (i < H * H) g_whl[i] = pack_hl(Ww[i]);
}

// ===========================================================================
// mma.sync m16n8k16 bf16 (portable tensor-core path; works on plain sm_103)
// ===========================================================================
__device__ __forceinline__ void mma_bf16(float c[4],
                                         uint32_t a0, uint32_t a1,
                                         uint32_t a2, uint32_t a3,
                                         uint32_t b0, uint32_t b1) {
    asm volatile(
        "mma.sync.aligned.m16n8k16.row.col.f32.bf16.bf16.f32 "
        "{%0,%1,%2,%3}, {%4,%5,%6,%7}, {%8,%9}, {%0,%1,%2,%3};"
        : "+f"(c[0]), "+f"(c[1]), "+f"(c[2]), "+f"(c[3])
        : "r"(a0), "r"(a1), "r"(a2), "r"(a3), "r"(b0), "r"(b1));
}

// ===========================================================================
// Permuted fragment-ready smem layout.
// Per row (32 rows), per 16-k block kb (32 blocks), four 16B t-groups:
//   [0:4)  hi pair (k = 16kb+2t, +1)     [4:8)  hi pair (k = 16kb+2t+8, +9)
//   [8:12) lo pair (k = 16kb+2t)         [12:16) lo pair (k = 16kb+2t+8)
// Row stride 2112 B (132 x 16B; 132 % 8 == 4 -> conflict-free LDS.128).
// ===========================================================================
constexpr int RSTR = 2112;
constexpr int SM_W = 0;                    // W panel:   32 * 2112 = 67584 B
constexpr int SM_A = 67584;                // A staging: 32 * 2112 = 67584 B
constexpr int SMEM_P2 = 135168;

// Load a 32-row x 512-k panel of packed {hi|lo} u32 into the permuted layout.
__device__ __forceinline__ void load_panel_permuted(
    char* dst, const uint32_t* __restrict__ src_plane, int row0, int tid)
{
    #pragma unroll
    for (int i = 0; i < 16; i++) {
        int j  = tid + i * 256;            // 0..4095
        int r  = j >> 7;                   // 0..31
        int k4 = (j & 127) * 4;            // 0..508, step 4
        uint4 v = *reinterpret_cast<const uint4*>(
            &src_plane[(size_t)(row0 + r) * 512 + k4]);
        uint32_t hi0 = __byte_perm(v.x, v.y, 0x7632);  // {hi(k4+1)|hi(k4)}
        uint32_t lo0 = __byte_perm(v.x, v.y, 0x5410);
        uint32_t hi1 = __byte_perm(v.z, v.w, 0x7632);  // {hi(k4+3)|hi(k4+2)}
        uint32_t lo1 = __byte_perm(v.z, v.w, 0x5410);
        int kb   = k4 >> 4;
        int rem  = k4 & 15;                // 0,4,8,12
        int slot = (rem >= 8) ? 4 : 0;     // byte offset for the +8 half
        int t0   = (rem & 7) >> 1;         // 0 or 2
        char* base = dst + r * RSTR + kb * 64 + t0 * 16 + slot;
        *reinterpret_cast<uint32_t*>(base)      = hi0;
        *reinterpret_cast<uint32_t*>(base + 8)  = lo0;
        *reinterpret_cast<uint32_t*>(base + 16) = hi1;  // t0+1 group
        *reinterpret_cast<uint32_t*>(base + 24) = lo1;
    }
}

// ===========================================================================
// Phase 1: xV = x @ Vw^T + Vb  (fp32 SIMT, known-good)
// ===========================================================================
__global__ void __launch_bounds__(256) phase1_gemm(
    const float* __restrict__ A,
    const float* __restrict__ W,
    const float* __restrict__ bias,
    float* __restrict__ C)
{
    constexpr int BM = 128, BN = 128, BK = 16;
    constexpr int K = I;
    constexpr int PAD = 4;
    __shared__ float As[BK][BM + PAD];
    __shared__ float Bs[BK][BN + PAD];

    const int tid = threadIdx.x;
    const int bn = blockIdx.x;
    const int bm = blockIdx.y;

    const float* Ap = A + (size_t)bm * BM * K;
    const float* Wp = W + (size_t)bn * BN * K;

    const int ty = tid / 16;
    const int tx = tid % 16;

    float acc[8][8];
    #pragma unroll
    for (int i = 0; i < 8; i++)
        #pragma unroll
        for (int j = 0; j < 8; j++) acc[i][j] = 0.0f;

    for (int k0 = 0; k0 < K; k0 += BK) {
        #pragma unroll
        for (int l = 0; l < 2; l++) {
            int f   = tid + l * 256;
            int row = f >> 2;
            int c4  = (f & 3) * 4;
            float4 av = *reinterpret_cast<const float4*>(Ap + (size_t)row * K + k0 + c4);
            As[c4 + 0][row] = av.x; As[c4 + 1][row] = av.y;
            As[c4 + 2][row] = av.z; As[c4 + 3][row] = av.w;
            float4 bv = *reinterpret_cast<const float4*>(Wp + (size_t)row * K + k0 + c4);
            Bs[c4 + 0][row] = bv.x; Bs[c4 + 1][row] = bv.y;
            Bs[c4 + 2][row] = bv.z; Bs[c4 + 3][row] = bv.w;
        }
        __syncthreads();
        #pragma unroll
        for (int k = 0; k < BK; k++) {
            float ar[8], br[8];
            *reinterpret_cast<float4*>(ar)     = *reinterpret_cast<const float4*>(&As[k][ty * 8]);
            *reinterpret_cast<float4*>(ar + 4) = *reinterpret_cast<const float4*>(&As[k][ty * 8 + 4]);
            *reinterpret_cast<float4*>(br)     = *reinterpret_cast<const float4*>(&Bs[k][tx * 8]);
            *reinterpret_cast<float4*>(br + 4) = *reinterpret_cast<const float4*>(&Bs[k][tx * 8 + 4]);
            #pragma unroll
            for (int i = 0; i < 8; i++)
                #pragma unroll
                for (int j = 0; j < 8; j++)
                    acc[i][j] = fmaf(ar[i], br[j], acc[i][j]);
        }
        __syncthreads();
    }
    const int rowb = bm * BM + ty * 8;
    const int colb = bn * BN + tx * 8;
    float bvals[8];
    #pragma unroll
    for (int j = 0; j < 8; j++) bvals[j] = bias[colb + j];
    #pragma unroll
    for (int i = 0; i < 8; i++) {
        float* cp = C + (size_t)(rowb + i) * H + colb;
        float4 v0, v1;
        v0.x = acc[i][0] + bvals[0]; v0.y = acc[i][1] + bvals[1];
        v0.z = acc[i][2] + bvals[2]; v0.w = acc[i][3] + bvals[3];
        v1.x = acc[i][4] + bvals[4]; v1.y = acc[i][5] + bvals[5];
        v1.z = acc[i][6] + bvals[6]; v1.w = acc[i][7] + bvals[7];
        *reinterpret_cast<float4*>(cp)     = v0;
        *reinterpret_cast<float4*>(cp + 4) = v1;
    }
}

// ===========================================================================
// Phase 2: persistent mma.sync bf16x3 recurrence.
// Grid: 128 CTAs = bm(0..7) x bn(0..15); tile 32(M) x 32(N); 256 threads.
// Warp w: mi = w>>2 (m0 = 16*mi), ni = w&3 (n0 = 8*ni) -> one m16n8 tile.
// ===========================================================================
__global__ void __launch_bounds__(256, 1) rnn_steps_mma(
    const float* __restrict__ Wb,
    float* __restrict__ io)
{
    extern __shared__ char smem[];

    const int tid = threadIdx.x;
    const int wid = tid >> 5;
    const int lane = tid & 31;
    const int bm  = blockIdx.x >> 4;           // 0..7
    const int bn  = blockIdx.x & 15;           // 0..15
    const int Rg0 = bm * 32;                   // first global row of tile
    const int cg0 = bn * 32;                   // first global col of tile

    const int mi = wid >> 2;                   // 0..1
    const int ni = wid & 3;                    // 0..3
    const int m0 = mi * 16;
    const int n0 = ni * 8;
    const int g  = lane >> 2;                  // 0..7
    const int t  = lane & 3;                   // 0..3

    // ---- Format resident W panel once (rows = out cols cg0..cg0+31) ----
    load_panel_permuted(smem + SM_W, g_whl, cg0, tid);

    // per-lane fragment addresses (constant across steps)
    const char* aP1 = smem + SM_A + (m0 + g) * RSTR + t * 16;
    const char* aP2 = aP1 + 8 * RSTR;
    const char* bP  = smem + SM_W + (n0 + g) * RSTR + t * 16;

    // per-lane output coords
    const int orow0 = Rg0 + m0 + g;            // and +8
    const int ocol  = cg0 + n0 + 2 * t;        // 2 cols
    const float2 wb2 = *reinterpret_cast<const float2*>(Wb + ocol);

    // ---- t = 0 : h_0 = tanh(xV_0 + Wb) ----
    {
        const int r   = Rg0 + (tid >> 3);
        const int c4  = cg0 + (tid & 7) * 4;
        float* p = io + (size_t)r * H + c4;
        float4 xv = *reinterpret_cast<const float4*>(p);
        const float4 wb4 = *reinterpret_cast<const float4*>(Wb + c4);
        float4 hv;
        hv.x = tanhf(xv.x + wb4.x); hv.y = tanhf(xv.y + wb4.y);
        hv.z = tanhf(xv.z + wb4.z); hv.w = tanhf(xv.w + wb4.w);
        *reinterpret_cast<float4*>(p) = hv;
        uint4 pk;
        pk.x = pack_hl(hv.x); pk.y = pack_hl(hv.y);
        pk.z = pack_hl(hv.z); pk.w = pack_hl(hv.w);
        *reinterpret_cast<uint4*>(&g_hl[0][(size_t)r * H + c4]) = pk;
    }
    __syncthreads();
    if (tid == 0) { __threadfence(); atomicAdd(&g_bar[bm], 1u); }

    // ---- steps 1 .. S-1 ----
    for (int t_step = 1; t_step < S; ++t_step) {
        // row-group barrier: all (bm,*) CTAs finished step t_step-1
        if (tid == 0) {
            const unsigned target = (unsigned)t_step * 16u;
            while (*((volatile unsigned int*)&g_bar[bm]) < target) { }
            __threadfence();
        }
        __syncthreads();

        // stage h_{t-1} rows Rg0..+32 into permuted A layout
        load_panel_permuted(smem + SM_A, &g_hl[(t_step - 1) & 1][0], Rg0, tid);
        __syncthreads();

        // prefetch xV for this lane's outputs (L2-resident)
        const float* ct = io + (size_t)t_step * BH;
        float2 xv0 = __ldcg(reinterpret_cast<const float2*>(
            ct + (size_t)orow0 * H + ocol));
        float2 xv1 = __ldcg(reinterpret_cast<const float2*>(
            ct + (size_t)(orow0 + 8) * H + ocol));

        float chh[4] = {0.f, 0.f, 0.f, 0.f};
        float chl[4] = {0.f, 0.f, 0.f, 0.f};
        float clh[4] = {0.f, 0.f, 0.f, 0.f};

        #pragma unroll 4
        for (int kb = 0; kb < 32; ++kb) {
            uint4 A1 = *reinterpret_cast<const uint4*>(aP1 + kb * 64);
            uint4 A2 = *reinterpret_cast<const uint4*>(aP2 + kb * 64);
            uint4 Bv = *reinterpret_cast<const uint4*>(bP  + kb * 64);
            // hi*hi
            mma_bf16(chh, A1.x, A2.x, A1.y, A2.y, Bv.x, Bv.y);
            // hi*lo
            mma_bf16(chl, A1.x, A2.x, A1.y, A2.y, Bv.z, Bv.w);
            // lo*hi
            mma_bf16(clh, A1.z, A2.z, A1.w, A2.w, Bv.x, Bv.y);
        }

        // epilogue: h = tanh(acc + xV + Wb)
        float s0 = chh[0] + chl[0] + clh[0];
        float s1 = chh[1] + chl[1] + clh[1];
        float s2 = chh[2] + chl[2] + clh[2];
        float s3 = chh[3] + chl[3] + clh[3];

        float h00 = tanhf(s0 + xv0.x + wb2.x);
        float h01 = tanhf(s1 + xv0.y + wb2.y);
        float h10 = tanhf(s2 + xv1.x + wb2.x);
        float h11 = tanhf(s3 + xv1.y + wb2.y);

        float* op0 = io + (size_t)t_step * BH + (size_t)orow0 * H + ocol;
        float* op1 = io + (size_t)t_step * BH + (size_t)(orow0 + 8) * H + ocol;
        *reinterpret_cast<float2*>(op0) = make_float2(h00, h01);
        *reinterpret_cast<float2*>(op1) = make_float2(h10, h11);

        uint32_t* sc = &g_hl[t_step & 1][0];
        *reinterpret_cast<uint2*>(&sc[(size_t)orow0 * H + ocol]) =
            make_uint2(pack_hl(h00), pack_hl(h01));
        *reinterpret_cast<uint2*>(&sc[(size_t)(orow0 + 8) * H + ocol]) =
            make_uint2(pack_hl(h10), pack_hl(h11));

        if (t_step == S - 1) {
            float* lp0 = io + (size_t)S * BH + (size_t)orow0 * H + ocol;
            float* lp1 = io + (size_t)S * BH + (size_t)(orow0 + 8) * H + ocol;
            *reinterpret_cast<float2*>(lp0) = make_float2(h00, h01);
            *reinterpret_cast<float2*>(lp1) = make_float2(h10, h11);
        }

        __syncthreads();
        if (tid == 0) { __threadfence(); atomicAdd(&g_bar[bm], 1u); }
    }
}

// ===========================================================================
// kernel_launch
// Inputs: x (S,B,I), Vw (H,I), Vb (H), Ww (H,H), Wb (H)
// Output: h_seq (S,B,H) ++ h_last (B,H), fp32
// ===========================================================================
extern "C" void kernel_launch(void* const* d_in, const int* in_sizes, int n_in,
                              void* d_out, int out_size)
{
    const float* x  = (const float*)d_in[0];
    const float* Vw = (const float*)d_in[1];
    const float* Vb = (const float*)d_in[2];
    const float* Ww = (const float*)d_in[3];
    const float* Wb = (const float*)d_in[4];
    float* out = (float*)d_out;

    static bool attr_done = false;
    if (!attr_done) {
        cudaFuncSetAttribute(rnn_steps_mma,
                             cudaFuncAttributeMaxDynamicSharedMemorySize,
                             SMEM_P2);
        attr_done = true;
    }

    reset_ctr<<<1, 32>>>();
    convert_W<<<(H * H + 255) / 256, 256>>>(Ww);

    dim3 g1(H / 128, M1 / 128);
    phase1_gemm<<<g1, 256>>>(x, Vw, Vb, out);

    rnn_steps_mma<<<128, 256, SMEM_P2>>>(Wb, out);
}

// round 6
// speedup vs baseline: 2.9080x; 1.0599x over previous
#include <cuda_runtime.h>
#include <cuda_bf16.h>
#include <math.h>
#include <stdint.h>

// Problem dims (fixed per reference)
constexpr int S = 512;
constexpr int B = 256;
constexpr int I = 512;
constexpr int H = 512;
constexpr int M1 = S * B;
constexpr int BH = B * H;

// Panel layout: per row, per 16-k block kb, four 16B t-groups:
//   [0:4) hi pair(2t,2t+1)  [4:8) hi pair(2t+8,2t+9)
//   [8:12) lo pair(2t)      [12:16) lo pair(2t+8)
// Row stride 2112 B (132*16B, 132%8==4 -> conflict-free LDS.128).
constexpr int RSTR = 2112;
constexpr int RU4  = 132;
constexpr int SM_W = 0;                  // W panel: 32*2112 = 67584
constexpr int SM_A = 32 * RSTR;          // A panel: 67584
constexpr int SMEM_P2 = 2 * 32 * RSTR;   // 135168

// ===========================================================================
// Static device scratch (allocation-free)
// ===========================================================================
__device__ uint4 g_hfmt[2][8][32 * RU4];   // h in fragment-ready format
__device__ uint32_t g_whl[H * H];          // packed {bf16 hi<<16 | bf16 lo} of Ww
__device__ unsigned int g_bar[8];          // per-bm-group barrier counters

__device__ __forceinline__ uint32_t pack_hl(float x) {
    __nv_bfloat16 h = __float2bfloat16(x);
    float r = x - __bfloat162float(h);
    __nv_bfloat16 l = __float2bfloat16(r);
    return (((uint32_t)__bfloat16_as_ushort(h)) << 16) |
           (uint32_t)__bfloat16_as_ushort(l);
}

// split pair (a,b) into bf16 hi-word and lo-word (a in low half)
__device__ __forceinline__ void split_pair(float a, float b,
                                           uint32_t& hiw, uint32_t& low) {
    __nv_bfloat16 ah = __float2bfloat16(a), bh = __float2bfloat16(b);
    float ar = a - __bfloat162float(ah);
    float br = b - __bfloat162float(bh);
    __nv_bfloat16 al = __float2bfloat16(ar), bl = __float2bfloat16(br);
    hiw = (((uint32_t)__bfloat16_as_ushort(bh)) << 16) | __bfloat16_as_ushort(ah);
    low = (((uint32_t)__bfloat16_as_ushort(bl)) << 16) | __bfloat16_as_ushort(al);
}

__global__ void reset_ctr() {
    if (threadIdx.x < 8) g_bar[threadIdx.x] = 0u;
}

__global__ void __launch_bounds__(256) convert_W(const float* __restrict__ Ww) {
    int i = blockIdx.x * blockDim.x + threadIdx.x;
    if (i < H * H) g_whl[i] = pack_hl(Ww[i]);
}

// ===========================================================================
// Barrier primitives (no membar.gl -> no L1 flush)
// ===========================================================================
__device__ __forceinline__ void bar_arrive(unsigned int* p) {
    asm volatile("red.release.gpu.add.u32 [%0], 1;" :: "l"(p) : "memory");
}
__device__ __forceinline__ unsigned int bar_peek(const unsigned int* p) {
    unsigned int v;
    asm volatile("ld.acquire.gpu.u32 %0, [%1];" : "=r"(v) : "l"(p) : "memory");
    return v;
}

// ===========================================================================
// mma.sync m16n8k16 bf16 (portable tensor-core path on sm_103)
// ===========================================================================
__device__ __forceinline__ void mma_bf16(float c[4],
                                         uint32_t a0, uint32_t a1,
                                         uint32_t a2, uint32_t a3,
                                         uint32_t b0, uint32_t b1) {
    asm volatile(
        "mma.sync.aligned.m16n8k16.row.col.f32.bf16.bf16.f32 "
        "{%0,%1,%2,%3}, {%4,%5,%6,%7}, {%8,%9}, {%0,%1,%2,%3};"
        : "+f"(c[0]), "+f"(c[1]), "+f"(c[2]), "+f"(c[3])
        : "r"(a0), "r"(a1), "r"(a2), "r"(a3), "r"(b0), "r"(b1));
}

// ===========================================================================
// Phase 1: xV = x @ Vw^T + Vb  (fp32 SIMT, known-good)
// ===========================================================================
__global__ void __launch_bounds__(256) phase1_gemm(
    const float* __restrict__ A,
    const float* __restrict__ W,
    const float* __restrict__ bias,
    float* __restrict__ C)
{
    constexpr int BM = 128, BN = 128, BK = 16;
    constexpr int K = I;
    constexpr int PAD = 4;
    __shared__ float As[BK][BM + PAD];
    __shared__ float Bs[BK][BN + PAD];

    const int tid = threadIdx.x;
    const int bn = blockIdx.x;
    const int bm = blockIdx.y;

    const float* Ap = A + (size_t)bm * BM * K;
    const float* Wp = W + (size_t)bn * BN * K;

    const int ty = tid / 16;
    const int tx = tid % 16;

    float acc[8][8];
    #pragma unroll
    for (int i = 0; i < 8; i++)
        #pragma unroll
        for (int j = 0; j < 8; j++) acc[i][j] = 0.0f;

    for (int k0 = 0; k0 < K; k0 += BK) {
        #pragma unroll
        for (int l = 0; l < 2; l++) {
            int f   = tid + l * 256;
            int row = f >> 2;
            int c4  = (f & 3) * 4;
            float4 av = *reinterpret_cast<const float4*>(Ap + (size_t)row * K + k0 + c4);
            As[c4 + 0][row] = av.x; As[c4 + 1][row] = av.y;
            As[c4 + 2][row] = av.z; As[c4 + 3][row] = av.w;
            float4 bv = *reinterpret_cast<const float4*>(Wp + (size_t)row * K + k0 + c4);
            Bs[c4 + 0][row] = bv.x; Bs[c4 + 1][row] = bv.y;
            Bs[c4 + 2][row] = bv.z; Bs[c4 + 3][row] = bv.w;
        }
        __syncthreads();
        #pragma unroll
        for (int k = 0; k < BK; k++) {
            float ar[8], br[8];
            *reinterpret_cast<float4*>(ar)     = *reinterpret_cast<const float4*>(&As[k][ty * 8]);
            *reinterpret_cast<float4*>(ar + 4) = *reinterpret_cast<const float4*>(&As[k][ty * 8 + 4]);
            *reinterpret_cast<float4*>(br)     = *reinterpret_cast<const float4*>(&Bs[k][tx * 8]);
            *reinterpret_cast<float4*>(br + 4) = *reinterpret_cast<const float4*>(&Bs[k][tx * 8 + 4]);
            #pragma unroll
            for (int i = 0; i < 8; i++)
                #pragma unroll
                for (int j = 0; j < 8; j++)
                    acc[i][j] = fmaf(ar[i], br[j], acc[i][j]);
        }
        __syncthreads();
    }
    const int rowb = bm * BM + ty * 8;
    const int colb = bn * BN + tx * 8;
    float bvals[8];
    #pragma unroll
    for (int j = 0; j < 8; j++) bvals[j] = bias[colb + j];
    #pragma unroll
    for (int i = 0; i < 8; i++) {
        float* cp = C + (size_t)(rowb + i) * H + colb;
        float4 v0, v1;
        v0.x = acc[i][0] + bvals[0]; v0.y = acc[i][1] + bvals[1];
        v0.z = acc[i][2] + bvals[2]; v0.w = acc[i][3] + bvals[3];
        v1.x = acc[i][4] + bvals[4]; v1.y = acc[i][5] + bvals[5];
        v1.z = acc[i][6] + bvals[6]; v1.w = acc[i][7] + bvals[7];
        *reinterpret_cast<float4*>(cp)     = v0;
        *reinterpret_cast<float4*>(cp + 4) = v1;
    }
}

// ===========================================================================
// Phase 2: persistent mma.sync bf16x3 recurrence.
// Grid: 128 CTAs = bm(0..7) x bn(0..15); tile 32(M) x 32(N); 128 threads.
// 4 warps: mi = wid>>1 (m0=16*mi), ni = wid&1 (n0=16*ni) -> m16n16 each.
// ===========================================================================
__global__ void __launch_bounds__(128, 1) rnn_steps_mma(
    const float* __restrict__ Wb,
    float* __restrict__ io)
{
    extern __shared__ char smem[];

    const int tid  = threadIdx.x;
    const int wid  = tid >> 5;
    const int lane = tid & 31;
    const int bm   = blockIdx.x >> 4;          // 0..7
    const int bn   = blockIdx.x & 15;          // 0..15
    const int Rg0  = bm * 32;
    const int cg0  = bn * 32;

    const int mi = wid >> 1;                   // 0..1
    const int ni = wid & 1;                    // 0..1
    const int m0 = mi * 16;
    const int n0 = ni * 16;
    const int g  = lane >> 2;                  // 0..7
    const int t  = lane & 3;                   // 0..3

    // ---- Format resident W panel once (rows = out cols cg0..cg0+31) ----
    for (int l = 0; l < 32; l++) {
        int j  = tid + (l << 7);               // 0..4095
        int r  = j >> 7;                       // 0..31
        int k4 = (j & 127) * 4;                // 0..508
        uint4 v = *reinterpret_cast<const uint4*>(
            &g_whl[(size_t)(cg0 + r) * 512 + k4]);
        uint32_t hi0 = __byte_perm(v.x, v.y, 0x7632);
        uint32_t lo0 = __byte_perm(v.x, v.y, 0x5410);
        uint32_t hi1 = __byte_perm(v.z, v.w, 0x7632);
        uint32_t lo1 = __byte_perm(v.z, v.w, 0x5410);
        int kb   = k4 >> 4;
        int rem  = k4 & 15;
        int slot = (rem >= 8) ? 4 : 0;
        int t0   = (rem & 7) >> 1;
        char* base = smem + SM_W + r * RSTR + kb * 64 + t0 * 16 + slot;
        *reinterpret_cast<uint32_t*>(base)      = hi0;
        *reinterpret_cast<uint32_t*>(base + 8)  = lo0;
        *reinterpret_cast<uint32_t*>(base + 16) = hi1;
        *reinterpret_cast<uint32_t*>(base + 24) = lo1;
    }

    // fragment pointers (constant across steps)
    const char* aB = smem + SM_A + (m0 + g) * RSTR + t * 16;
    const char* bB = smem + SM_W + (n0 + g) * RSTR + t * 16;

    // per-lane output coords
    const int orow0 = Rg0 + m0 + g;            // and +8
    const int c0    = cg0 + n0 + 2 * t;        // tile0 cols c0,c0+1; tile1 +8
    const float2 wbA = *reinterpret_cast<const float2*>(Wb + c0);
    const float2 wbB = *reinterpret_cast<const float2*>(Wb + c0 + 8);
    // g_hfmt granule byte offset within a row (hi word covers k and k+8)
    const int goff = ((cg0 + n0) >> 4) * 64 + t * 16;

    // ---- t = 0 : h_0 = tanh(xV_0 + Wb) ----
    {
        const int r  = tid >> 2;               // 0..31 local row
        const int c8 = (tid & 3) * 8;          // 0,8,16,24 local col
        const int gr = Rg0 + r;
        const float* xvp = io + (size_t)gr * H + cg0 + c8;
        float4 xv0 = __ldcg(reinterpret_cast<const float4*>(xvp));
        float4 xv1 = __ldcg(reinterpret_cast<const float4*>(xvp + 4));
        const float4 wb0 = *reinterpret_cast<const float4*>(Wb + cg0 + c8);
        const float4 wb1 = *reinterpret_cast<const float4*>(Wb + cg0 + c8 + 4);
        float h[8];
        h[0] = tanhf(xv0.x + wb0.x); h[1] = tanhf(xv0.y + wb0.y);
        h[2] = tanhf(xv0.z + wb0.z); h[3] = tanhf(xv0.w + wb0.w);
        h[4] = tanhf(xv1.x + wb1.x); h[5] = tanhf(xv1.y + wb1.y);
        h[6] = tanhf(xv1.z + wb1.z); h[7] = tanhf(xv1.w + wb1.w);
        float* op = io + (size_t)gr * H + cg0 + c8;
        *reinterpret_cast<float4*>(op)     = make_float4(h[0], h[1], h[2], h[3]);
        *reinterpret_cast<float4*>(op + 4) = make_float4(h[4], h[5], h[6], h[7]);
        char* gbase = reinterpret_cast<char*>(&g_hfmt[0][bm][0]) + r * RSTR;
        #pragma unroll
        for (int p = 0; p < 4; p++) {
            int k   = c8 + 2 * p;              // local col pair
            int km  = k & 15;
            int tg  = (km & 7) >> 1;
            int sl  = (km >= 8) ? 4 : 0;
            int kb  = (cg0 + k) >> 4;
            uint32_t hiw, low;
            split_pair(h[2 * p], h[2 * p + 1], hiw, low);
            char* ptr = gbase + kb * 64 + tg * 16 + sl;
            __stcg(reinterpret_cast<uint32_t*>(ptr), hiw);
            __stcg(reinterpret_cast<uint32_t*>(ptr + 8), low);
        }
    }
    __syncthreads();
    if (tid == 0) bar_arrive(&g_bar[bm]);

    // ---- steps 1 .. S-1 ----
    for (int ts = 1; ts < S; ++ts) {
        // xV prefetch (independent of h_{t-1}; issue before the barrier)
        const float* iot = io + (size_t)ts * BH;
        float2 xva0 = __ldcg(reinterpret_cast<const float2*>(iot + (size_t)orow0 * H + c0));
        float2 xva1 = __ldcg(reinterpret_cast<const float2*>(iot + (size_t)orow0 * H + c0 + 8));
        float2 xvb0 = __ldcg(reinterpret_cast<const float2*>(iot + (size_t)(orow0 + 8) * H + c0));
        float2 xvb1 = __ldcg(reinterpret_cast<const float2*>(iot + (size_t)(orow0 + 8) * H + c0 + 8));

        // row-group barrier: all (bm,*) CTAs finished step ts-1
        if (tid == 0) {
            const unsigned target = (unsigned)ts * 16u;
            while (bar_peek(&g_bar[bm]) < target) { }
        }
        __syncthreads();

        // stage h_{t-1} panel: straight uint4 copy (already fragment-format)
        const uint4* src = &g_hfmt[(ts + 1) & 1][bm][0];
        #pragma unroll 8
        for (int l = 0; l < 32; l++) {
            int j = tid + (l << 7);            // 0..4095
            int r = j >> 7;
            int c = j & 127;
            uint4 v = __ldcg(src + r * RU4 + c);
            *reinterpret_cast<uint4*>(smem + SM_A + r * RSTR + c * 16) = v;
        }
        __syncthreads();

        float chh0[4] = {0.f, 0.f, 0.f, 0.f};
        float chl0[4] = {0.f, 0.f, 0.f, 0.f};
        float clh0[4] = {0.f, 0.f, 0.f, 0.f};
        float chh1[4] = {0.f, 0.f, 0.f, 0.f};
        float chl1[4] = {0.f, 0.f, 0.f, 0.f};
        float clh1[4] = {0.f, 0.f, 0.f, 0.f};

        #pragma unroll 8
        for (int kb = 0; kb < 32; ++kb) {
            uint4 A1 = *reinterpret_cast<const uint4*>(aB + kb * 64);
            uint4 A2 = *reinterpret_cast<const uint4*>(aB + 8 * RSTR + kb * 64);
            uint4 B1 = *reinterpret_cast<const uint4*>(bB + kb * 64);
            uint4 B2 = *reinterpret_cast<const uint4*>(bB + 8 * RSTR + kb * 64);
            mma_bf16(chh0, A1.x, A2.x, A1.y, A2.y, B1.x, B1.y);   // hi*hi n-tile0
            mma_bf16(chh1, A1.x, A2.x, A1.y, A2.y, B2.x, B2.y);   // hi*hi n-tile1
            mma_bf16(chl0, A1.x, A2.x, A1.y, A2.y, B1.z, B1.w);   // hi*lo
            mma_bf16(chl1, A1.x, A2.x, A1.y, A2.y, B2.z, B2.w);
            mma_bf16(clh0, A1.z, A2.z, A1.w, A2.w, B1.x, B1.y);   // lo*hi
            mma_bf16(clh1, A1.z, A2.z, A1.w, A2.w, B2.x, B2.y);
        }

        // epilogue: h = tanh(acc + xV + Wb)
        float h00 = tanhf(chh0[0] + chl0[0] + clh0[0] + xva0.x + wbA.x);
        float h01 = tanhf(chh0[1] + chl0[1] + clh0[1] + xva0.y + wbA.y);
        float h08 = tanhf(chh1[0] + chl1[0] + clh1[0] + xva1.x + wbB.x);
        float h09 = tanhf(chh1[1] + chl1[1] + clh1[1] + xva1.y + wbB.y);
        float h20 = tanhf(chh0[2] + chl0[2] + clh0[2] + xvb0.x + wbA.x);
        float h21 = tanhf(chh0[3] + chl0[3] + clh0[3] + xvb0.y + wbA.y);
        float h28 = tanhf(chh1[2] + chl1[2] + clh1[2] + xvb1.x + wbB.x);
        float h29 = tanhf(chh1[3] + chl1[3] + clh1[3] + xvb1.y + wbB.y);

        float* op0 = io + (size_t)ts * BH + (size_t)orow0 * H + c0;
        float* op1 = io + (size_t)ts * BH + (size_t)(orow0 + 8) * H + c0;
        *reinterpret_cast<float2*>(op0)     = make_float2(h00, h01);
        *reinterpret_cast<float2*>(op0 + 8) = make_float2(h08, h09);
        *reinterpret_cast<float2*>(op1)     = make_float2(h20, h21);
        *reinterpret_cast<float2*>(op1 + 8) = make_float2(h28, h29);

        // write fragment-format h for next step
        {
            char* gb = reinterpret_cast<char*>(&g_hfmt[ts & 1][bm][0]);
            uint32_t hw0, lw0, hw1, lw1;
            split_pair(h00, h01, hw0, lw0);
            split_pair(h08, h09, hw1, lw1);
            char* p0 = gb + (m0 + g) * RSTR + goff;
            __stcg(reinterpret_cast<uint2*>(p0),     make_uint2(hw0, hw1));
            __stcg(reinterpret_cast<uint2*>(p0 + 8), make_uint2(lw0, lw1));
            split_pair(h20, h21, hw0, lw0);
            split_pair(h28, h29, hw1, lw1);
            char* p1 = gb + (m0 + g + 8) * RSTR + goff;
            __stcg(reinterpret_cast<uint2*>(p1),     make_uint2(hw0, hw1));
            __stcg(reinterpret_cast<uint2*>(p1 + 8), make_uint2(lw0, lw1));
        }

        if (ts == S - 1) {
            float* lp0 = io + (size_t)S * BH + (size_t)orow0 * H + c0;
            float* lp1 = io + (size_t)S * BH + (size_t)(orow0 + 8) * H + c0;
            *reinterpret_cast<float2*>(lp0)     = make_float2(h00, h01);
            *reinterpret_cast<float2*>(lp0 + 8) = make_float2(h08, h09);
            *reinterpret_cast<float2*>(lp1)     = make_float2(h20, h21);
            *reinterpret_cast<float2*>(lp1 + 8) = make_float2(h28, h29);
        }

        __syncthreads();
        if (tid == 0) bar_arrive(&g_bar[bm]);
    }
}

// ===========================================================================
// kernel_launch
// Inputs: x (S,B,I), Vw (H,I), Vb (H), Ww (H,H), Wb (H)
// Output: h_seq (S,B,H) ++ h_last (B,H), fp32
// ===========================================================================
extern "C" void kernel_launch(void* const* d_in, const int* in_sizes, int n_in,
                              void* d_out, int out_size)
{
    const float* x  = (const float*)d_in[0];
    const float* Vw = (const float*)d_in[1];
    const float* Vb = (const float*)d_in[2];
    const float* Ww = (const float*)d_in[3];
    const float* Wb = (const float*)d_in[4];
    float* out = (float*)d_out;

    static bool attr_done = false;
    if (!attr_done) {
        cudaFuncSetAttribute(rnn_steps_mma,
                             cudaFuncAttributeMaxDynamicSharedMemorySize,
                             SMEM_P2);
        attr_done = true;
    }

    reset_ctr<<<1, 32>>>();
    convert_W<<<(H * H + 255) / 256, 256>>>(Ww);

    dim3 g1(H / 128, M1 / 128);
    phase1_gemm<<<g1, 256>>>(x, Vw, Vb, out);

    rnn_steps_mma<<<128, 128, SMEM_P2>>>(Wb, out);
}